// round 2
// baseline (speedup 1.0000x reference)
#include <cuda_runtime.h>

#define D      1024
#define TPB    256
#define NW     (TPB / 32)
#define FACTOR 4
#define LN_EPS 1e-5f

// Block-wide reduction of N float values (sum), result broadcast to all threads.
template <int N>
__device__ __forceinline__ void block_reduce(float (&v)[N],
                                             volatile float (*sred)[3],
                                             volatile float* sbc) {
    const int lane = threadIdx.x & 31;
    const int wid  = threadIdx.x >> 5;
    #pragma unroll
    for (int off = 16; off; off >>= 1)
        #pragma unroll
        for (int i = 0; i < N; i++)
            v[i] += __shfl_xor_sync(0xffffffffu, v[i], off);
    if (lane == 0)
        #pragma unroll
        for (int i = 0; i < N; i++) sred[wid][i] = v[i];
    __syncthreads();
    if (wid == 0) {
        #pragma unroll
        for (int i = 0; i < N; i++)
            v[i] = (lane < NW) ? sred[lane][i] : 0.0f;
        #pragma unroll
        for (int off = NW / 2; off; off >>= 1)
            #pragma unroll
            for (int i = 0; i < N; i++)
                v[i] += __shfl_xor_sync(0xffffffffu, v[i], off);
        if (lane == 0)
            #pragma unroll
            for (int i = 0; i < N; i++) sbc[i] = v[i];
    }
    __syncthreads();
    #pragma unroll
    for (int i = 0; i < N; i++) v[i] = sbc[i];
}

__global__ __launch_bounds__(TPB)
void attn_ds_kernel(const float* __restrict__ gq,
                    const float* __restrict__ gk,
                    const float* __restrict__ gv,
                    const float* __restrict__ glw,
                    const float* __restrict__ glb,
                    float* __restrict__ gout) {
    __shared__ float sred[NW][3];
    __shared__ float sbc[3];

    const int r = blockIdx.x;            // output row index in [0, B*Sq)
    const int t = threadIdx.x;           // each thread owns 4 consecutive elems
    const size_t qoff  = (size_t)r * D;
    const size_t kvoff = (size_t)r * FACTOR * D;   // k/v row 4*r + f

    // ---- Front-batched loads: 11 x LDG.128 per thread (max MLP) ----
    const float4 qv = reinterpret_cast<const float4*>(gq + qoff)[t];
    float4 kr[FACTOR], vr[FACTOR];
    #pragma unroll
    for (int f = 0; f < FACTOR; f++)
        kr[f] = reinterpret_cast<const float4*>(gk + kvoff + (size_t)f * D)[t];
    #pragma unroll
    for (int f = 0; f < FACTOR; f++)
        vr[f] = reinterpret_cast<const float4*>(gv + kvoff + (size_t)f * D)[t];
    const float4 wv = reinterpret_cast<const float4*>(glw)[t];
    const float4 bv = reinterpret_cast<const float4*>(glb)[t];

    const float qe[4] = {qv.x, qv.y, qv.z, qv.w};
    const float we[4] = {wv.x, wv.y, wv.z, wv.w};
    const float be[4] = {bv.x, bv.y, bv.z, bv.w};

    const float inv_d = 1.0f / (float)D;

    // ---- q layernorm stats ----
    {
        float red2[2] = {0.0f, 0.0f};
        #pragma unroll
        for (int i = 0; i < 4; i++) {
            red2[0] += qe[i];
            red2[1] += qe[i] * qe[i];
        }
        block_reduce<2>(red2, sred, sbc);
        const float muq = red2[0] * inv_d;
        const float rsq = rsqrtf(red2[1] * inv_d - muq * muq + LN_EPS);

        // qn*w kept per-thread; C1 = sum(qn*w), C2 = sum(qn*b)
        float tq[4];
        float redc[2] = {0.0f, 0.0f};
        #pragma unroll
        for (int i = 0; i < 4; i++) {
            const float qn = (qe[i] - muq) * rsq * we[i] + be[i];
            tq[i] = qn * we[i];
            redc[0] += tq[i];
            redc[1] += qn * be[i];
        }
        block_reduce<2>(redc, sred, sbc);
        const float C1 = redc[0];
        const float C2 = redc[1];

        float acc[4] = {0.0f, 0.0f, 0.0f, 0.0f};
        float accB = 0.0f;

        #pragma unroll
        for (int f = 0; f < FACTOR; f++) {
            const float ke[4] = {kr[f].x, kr[f].y, kr[f].z, kr[f].w};
            const float ve[4] = {vr[f].x, vr[f].y, vr[f].z, vr[f].w};

            // fused k-row reduction: sum, sumsq, dot(qn*w, k)
            float r3[3] = {0.0f, 0.0f, 0.0f};
            #pragma unroll
            for (int i = 0; i < 4; i++) {
                r3[0] += ke[i];
                r3[1] += ke[i] * ke[i];
                r3[2] += tq[i] * ke[i];
            }
            block_reduce<3>(r3, sred, sbc);
            const float muk = r3[0] * inv_d;
            const float rsk = rsqrtf(r3[1] * inv_d - muk * muk + LN_EPS);
            const float wf  = rsk * (r3[2] - muk * C1) + C2;   // logit (no softmax)

            // v-row stats
            float r2[2] = {0.0f, 0.0f};
            #pragma unroll
            for (int i = 0; i < 4; i++) {
                r2[0] += ve[i];
                r2[1] += ve[i] * ve[i];
            }
            block_reduce<2>(r2, sred, sbc);
            const float muv = r2[0] * inv_d;
            const float rsv = rsqrtf(r2[1] * inv_d - muv * muv + LN_EPS);

            const float wrs = wf * rsv;
            #pragma unroll
            for (int i = 0; i < 4; i++)
                acc[i] += wrs * (ve[i] - muv);
            accB += wf;
        }

        // out = q + lw * acc + lb * accB
        float4 o;
        o.x = qe[0] + we[0] * acc[0] + be[0] * accB;
        o.y = qe[1] + we[1] * acc[1] + be[1] * accB;
        o.z = qe[2] + we[2] * acc[2] + be[2] * accB;
        o.w = qe[3] + we[3] * acc[3] + be[3] * accB;
        reinterpret_cast<float4*>(gout + qoff)[t] = o;
    }
}

extern "C" void kernel_launch(void* const* d_in, const int* in_sizes, int n_in,
                              void* d_out, int out_size) {
    const float* q  = (const float*)d_in[0];
    const float* k  = (const float*)d_in[1];
    const float* v  = (const float*)d_in[2];
    const float* lw = (const float*)d_in[3];
    const float* lb = (const float*)d_in[4];
    float* out = (float*)d_out;

    const int rows = out_size / D;   // B * Sq = 8192
    attn_ds_kernel<<<rows, TPB>>>(q, k, v, lw, lb, out);
}